// round 14
// baseline (speedup 1.0000x reference)
#include <cuda_runtime.h>
#include <cstdint>

#define S_DIM 16
#define M_DIM 768
#define N_DIM 1024
#define ROWS_PER_BLK 2
#define STAGE_ROWS 3              // exactly rows r, r+1 feed blend row r (all groups)
#define LPAD 68                   // covers x0 >= -65
#define RPAD 4
#define RSTRIDE (LPAD + N_DIM + RPAD)   // 1096 floats = 4384 B
#define ROW_BYTES (N_DIM * 4)     // 4096
#define LR_OFF (STAGE_ROWS * RSTRIDE)   // lr staging: 2 x 1024 floats (16B aligned)
#define VEC_PER_ROW (RSTRIDE / 4)       // 274 float4 per padded row
#define INVALID_VAL 100.0f

__device__ __forceinline__ uint32_t smem_u32(const void* p) {
    return (uint32_t)__cvta_generic_to_shared(p);
}

__global__ __launch_bounds__(256) void lr_distance_kernel(
    const float* __restrict__ lr,
    const float* __restrict__ rl,
    float* __restrict__ out)
{
    // 3 staged rl rows (blend reuses rows 0 & 2 in-place) + 2 lr rows = 21344 B
    //   -> 8 blocks/SM (64 warps), vs R13's 30 KB / 7 blocks
    __shared__ __align__(16) float sm[STAGE_ROWS * RSTRIDE + ROWS_PER_BLK * N_DIM];
    __shared__ __align__(8)  uint64_t mbar;

    const int tid   = threadIdx.x;
    const int bid   = blockIdx.x;
    const int s     = bid / (M_DIM / ROWS_PER_BLK);
    const int grp   = bid % (M_DIM / ROWS_PER_BLK);
    const int ybase = grp * ROWS_PER_BLK;
    // y0(y) = y-1 for y <= M/2-1, y for y >= M/2  (iy = y*M/(M-1) - 0.5)
    const int g0    = ybase - (ybase < (M_DIM / 2) ? 1 : 0);  // first staged row

    const int sbase = s * (M_DIM * N_DIM);
    const float* __restrict__ img = rl + sbase;
    const uint32_t bar = smem_u32(&mbar);

    // Thread 0: init barrier, proxy-fence, issue all bulk copies (program-ordered).
    if (tid == 0) {
        asm volatile("mbarrier.init.shared.b64 [%0], %1;" :: "r"(bar), "r"(1) : "memory");
        asm volatile("fence.proxy.async.shared::cta;" ::: "memory");
        int n_valid = 0;
        #pragma unroll
        for (int r = 0; r < STAGE_ROWS; r++) {
            int g = g0 + r;
            if (g >= 0 && g < M_DIM) n_valid++;
        }
        asm volatile("mbarrier.arrive.expect_tx.shared.b64 _, [%0], %1;"
                     :: "r"(bar), "r"((n_valid + ROWS_PER_BLK) * ROW_BYTES) : "memory");
        // rl rows (padded destinations)
        #pragma unroll
        for (int r = 0; r < STAGE_ROWS; r++) {
            int g = g0 + r;
            if (g >= 0 && g < M_DIM) {
                uint32_t dst = smem_u32(sm + r * RSTRIDE + LPAD);
                const float* src = img + g * N_DIM;
                asm volatile(
                    "cp.async.bulk.shared::cta.global.mbarrier::complete_tx::bytes "
                    "[%0], [%1], %2, [%3];"
                    :: "r"(dst), "l"(src), "r"(ROW_BYTES), "r"(bar) : "memory");
            }
        }
        // lr rows (dense destinations)
        #pragma unroll
        for (int r = 0; r < ROWS_PER_BLK; r++) {
            uint32_t dst = smem_u32(sm + LR_OFF + r * N_DIM);
            const float* src = lr + sbase + (ybase + r) * N_DIM;
            asm volatile(
                "cp.async.bulk.shared::cta.global.mbarrier::complete_tx::bytes "
                "[%0], [%1], %2, [%3];"
                :: "r"(dst), "l"(src), "r"(ROW_BYTES), "r"(bar) : "memory");
        }
    }

    // Zero staged-row pads (72 floats/row, disjoint from TMA destinations)
    for (int v = tid; v < STAGE_ROWS * (LPAD + RPAD); v += 256) {
        int r = v / (LPAD + RPAD);
        int p = v % (LPAD + RPAD);
        int idx = (p < LPAD) ? p : (LPAD + N_DIM + (p - LPAD));
        sm[r * RSTRIDE + idx] = 0.0f;
    }
    // Zero out-of-bounds staged rows (only first/last group of each image)
    #pragma unroll
    for (int r = 0; r < STAGE_ROWS; r++) {
        int g = g0 + r;
        if (g < 0 || g >= M_DIM) {
            for (int c = tid; c < N_DIM / 4; c += 256)
                reinterpret_cast<float4*>(sm + r * RSTRIDE + LPAD)[c] =
                    make_float4(0.0f, 0.0f, 0.0f, 0.0f);
        }
    }
    __syncthreads();   // publishes pad stores + mbarrier init to all threads

    // Wait for all bulk copies (acquire orders subsequent LDS after TMA writes)
    {
        uint32_t done;
        do {
            asm volatile(
                "{\n\t.reg .pred p;\n\t"
                "mbarrier.try_wait.parity.acquire.cta.shared::cta.b64 p, [%1], %2;\n\t"
                "selp.b32 %0, 1, 0, p;\n\t}"
                : "=r"(done) : "r"(bar), "r"(0u) : "memory");
        } while (!done);
    }

    // Per-row vertical weight (blend row r reads staged rows r, r+1 — all groups)
    float wy1v[ROWS_PER_BLK];
    #pragma unroll
    for (int r = 0; r < ROWS_PER_BLK; r++) {
        const int y = ybase + r;
        float yl  = 2.0f * (float)y / (float)(M_DIM - 1) - 1.0f;
        float iy  = ((yl + 1.0f) * (float)M_DIM - 1.0f) * 0.5f;
        wy1v[r] = iy - floorf(iy);
    }

    // ── In-place vertical pre-blend ──
    // blend1 (rows 1,2) -> regs; barrier; store into row2 region + blend0 (rows 0,1)
    // -> regs; barrier; store into row0 region.
    {
        const float4* __restrict__ r0v = reinterpret_cast<const float4*>(sm);
        const float4* __restrict__ r1v = reinterpret_cast<const float4*>(sm + RSTRIDE);
        const float4* __restrict__ r2v = reinterpret_cast<const float4*>(sm + 2 * RSTRIDE);
        float4* __restrict__ d2 = reinterpret_cast<float4*>(sm + 2 * RSTRIDE);
        float4* __restrict__ d0 = reinterpret_cast<float4*>(sm);

        float4 b1[2];
        int    cs[2];
        #pragma unroll
        for (int k = 0; k < 2; k++) {
            int c = tid + k * 256;
            cs[k] = (c < VEC_PER_ROW) ? c : -1;
            int cc = (cs[k] >= 0) ? c : 0;
            float4 va = r1v[cc], vb = r2v[cc], o;
            float w = wy1v[1];
            o.x = fmaf(w, vb.x - va.x, va.x);
            o.y = fmaf(w, vb.y - va.y, va.y);
            o.z = fmaf(w, vb.z - va.z, va.z);
            o.w = fmaf(w, vb.w - va.w, va.w);
            b1[k] = o;
        }
        __syncthreads();                       // all reads of row2 complete

        float4 b0[2];
        #pragma unroll
        for (int k = 0; k < 2; k++) {
            if (cs[k] >= 0) d2[cs[k]] = b1[k]; // blend1 -> row2 region
            int cc = (cs[k] >= 0) ? cs[k] : 0;
            float4 va = r0v[cc], vb = r1v[cc], o;
            float w = wy1v[0];
            o.x = fmaf(w, vb.x - va.x, va.x);
            o.y = fmaf(w, vb.y - va.y, va.y);
            o.z = fmaf(w, vb.z - va.z, va.z);
            o.w = fmaf(w, vb.w - va.w, va.w);
            b0[k] = o;
        }
        __syncthreads();                       // all reads of rows 0,1 complete

        #pragma unroll
        for (int k = 0; k < 2; k++)
            if (cs[k] >= 0) d0[cs[k]] = b0[k]; // blend0 -> row0 region
    }
    __syncthreads();                           // blends visible to all

    // ── Gather: lr from smem (coalesced LDS.128) + 2 random scalar taps ──
    const int   xs  = tid * 4;
    const float xlb = (float)xs;
    const float RCP_SCALE = 2.0f / 1023.0f;

    #pragma unroll
    for (int r = 0; r < ROWS_PER_BLK; r++) {
        const int y = ybase + r;
        const float* __restrict__ rowb = sm + (2 * r) * RSTRIDE;  // blend0@row0, blend1@row2

        float4 dv = *reinterpret_cast<const float4*>(sm + LR_OFF + r * N_DIM + xs);
        float dd[4] = {dv.x, dv.y, dv.z, dv.w};
        float res[4];

        #pragma unroll
        for (int j = 0; j < 4; j++) {
            float d  = dd[j];
            float xr = (xlb + (float)j) - d;

            float t   = fmaf(xr, RCP_SCALE, -1.0f);   // xr_normed
            float ix  = fmaf(t, 512.0f, 511.5f);      // ((t+1)*1024 - 1)*0.5
            float x0f = floorf(ix);
            float wx1 = ix - x0f;
            int   idx = (int)x0f + LPAD;              // in [3, 1092]; pads absorb OOB

            float b0 = rowb[idx];
            float b1 = rowb[idx + 1];
            float warped = fmaf(wx1, b1 - b0, b0);

            float dist = fabsf(d + warped);
            // d in [0,64) => xr = x-d <= 1023 < N always; only left OOB possible
            res[j] = (xr < 0.0f) ? INVALID_VAL : dist;
        }

        *reinterpret_cast<float4*>(out + sbase + y * N_DIM + xs) =
            make_float4(res[0], res[1], res[2], res[3]);
    }
}

extern "C" void kernel_launch(void* const* d_in, const int* in_sizes, int n_in,
                              void* d_out, int out_size)
{
    const float* lr = (const float*)d_in[0];
    const float* rl = (const float*)d_in[1];
    float* out = (float*)d_out;

    int blocks = S_DIM * (M_DIM / ROWS_PER_BLK);   // 16 * 384 = 6144
    lr_distance_kernel<<<blocks, 256>>>(lr, rl, out);
}

// round 15
// speedup vs baseline: 1.1026x; 1.1026x over previous
#include <cuda_runtime.h>
#include <cstdint>

#define S_DIM 16
#define M_DIM 768
#define N_DIM 1024
#define ROWS_PER_BLK 2
#define STAGE_ROWS 3              // exactly y0(ybase) .. y0(ybase+1)+1
#define LPAD 4                    // only blend[-1] must be zero for VALID outputs
#define RPAD 4                    // only blend[1024] must be zero
#define RSTRIDE (LPAD + N_DIM + RPAD)   // 1032 floats = 4128 B (16B multiple)
#define ROW_BYTES (N_DIM * 4)     // 4096
#define LR_OFF (STAGE_ROWS * RSTRIDE)           // lr staging: 2 x 1024 floats
#define BL_OFF (LR_OFF + ROWS_PER_BLK * N_DIM)  // blend buffer base (floats)
#define VEC_PER_ROW (RSTRIDE / 4)       // 258 float4 per padded row
#define INVALID_VAL 100.0f

__device__ __forceinline__ uint32_t smem_u32(const void* p) {
    return (uint32_t)__cvta_generic_to_shared(p);
}

__global__ __launch_bounds__(256) void lr_distance_kernel(
    const float* __restrict__ lr,
    const float* __restrict__ rl,
    float* __restrict__ out)
{
    // 3 staged rl rows + 2 lr rows + 2 blend rows = 28832 B -> 8 blocks/SM (64 warps).
    // NOTE: gather idx can be as low as LPAD-65 = -61 (only for INVALID outputs,
    // which are overwritten with 100.0). Those reads land in earlier regions of
    // this array — memory-safe garbage. Valid outputs only touch [3, 1028], whose
    // boundary entries (pads) are zeroed below.
    __shared__ __align__(16) float sm[BL_OFF + ROWS_PER_BLK * RSTRIDE];
    __shared__ __align__(8)  uint64_t mbar;

    const int tid   = threadIdx.x;
    const int bid   = blockIdx.x;
    const int s     = bid / (M_DIM / ROWS_PER_BLK);
    const int grp   = bid % (M_DIM / ROWS_PER_BLK);
    const int ybase = grp * ROWS_PER_BLK;
    // y0(y) = y-1 for y <= M/2-1, y for y >= M/2  (iy = y*M/(M-1) - 0.5)
    const int g0    = ybase - (ybase < (M_DIM / 2) ? 1 : 0);  // first staged row

    const int sbase = s * (M_DIM * N_DIM);
    const float* __restrict__ img = rl + sbase;
    const uint32_t bar = smem_u32(&mbar);

    // Thread 0: init barrier, proxy-fence, issue all bulk copies (program-ordered).
    if (tid == 0) {
        asm volatile("mbarrier.init.shared.b64 [%0], %1;" :: "r"(bar), "r"(1) : "memory");
        asm volatile("fence.proxy.async.shared::cta;" ::: "memory");
        int n_valid = 0;
        #pragma unroll
        for (int r = 0; r < STAGE_ROWS; r++) {
            int g = g0 + r;
            if (g >= 0 && g < M_DIM) n_valid++;
        }
        asm volatile("mbarrier.arrive.expect_tx.shared.b64 _, [%0], %1;"
                     :: "r"(bar), "r"((n_valid + ROWS_PER_BLK) * ROW_BYTES) : "memory");
        // rl rows (padded destinations; LPAD*4 = 16 B -> dst stays 16B aligned)
        #pragma unroll
        for (int r = 0; r < STAGE_ROWS; r++) {
            int g = g0 + r;
            if (g >= 0 && g < M_DIM) {
                uint32_t dst = smem_u32(sm + r * RSTRIDE + LPAD);
                const float* src = img + g * N_DIM;
                asm volatile(
                    "cp.async.bulk.shared::cta.global.mbarrier::complete_tx::bytes "
                    "[%0], [%1], %2, [%3];"
                    :: "r"(dst), "l"(src), "r"(ROW_BYTES), "r"(bar) : "memory");
            }
        }
        // lr rows (dense destinations)
        #pragma unroll
        for (int r = 0; r < ROWS_PER_BLK; r++) {
            uint32_t dst = smem_u32(sm + LR_OFF + r * N_DIM);
            const float* src = lr + sbase + (ybase + r) * N_DIM;
            asm volatile(
                "cp.async.bulk.shared::cta.global.mbarrier::complete_tx::bytes "
                "[%0], [%1], %2, [%3];"
                :: "r"(dst), "l"(src), "r"(ROW_BYTES), "r"(bar) : "memory");
        }
    }

    // Zero staged-row pads (8 floats/row: [0,4) and [1028,1032)) — 24 entries total.
    if (tid < STAGE_ROWS * (LPAD + RPAD)) {
        int r = tid / (LPAD + RPAD);
        int p = tid % (LPAD + RPAD);
        int idx = (p < LPAD) ? p : (N_DIM + p);
        sm[r * RSTRIDE + idx] = 0.0f;
    }
    // Zero out-of-bounds staged rows (only first/last group of each image)
    #pragma unroll
    for (int r = 0; r < STAGE_ROWS; r++) {
        int g = g0 + r;
        if (g < 0 || g >= M_DIM) {
            for (int c = tid; c < N_DIM / 4; c += 256)
                reinterpret_cast<float4*>(sm + r * RSTRIDE + LPAD)[c] =
                    make_float4(0.0f, 0.0f, 0.0f, 0.0f);
        }
    }
    __syncthreads();   // publishes pad stores + mbarrier init to all threads

    // Wait for all bulk copies (acquire orders subsequent LDS after TMA writes)
    {
        uint32_t done;
        do {
            asm volatile(
                "{\n\t.reg .pred p;\n\t"
                "mbarrier.try_wait.parity.acquire.cta.shared::cta.b64 p, [%1], %2;\n\t"
                "selp.b32 %0, 1, 0, p;\n\t}"
                : "=r"(done) : "r"(bar), "r"(0u) : "memory");
        } while (!done);
    }

    // ── Vertical pre-blend: one padded row per output row, fully vectorized ──
    #pragma unroll
    for (int r = 0; r < ROWS_PER_BLK; r++) {
        const int y = ybase + r;
        float yl  = 2.0f * (float)y / (float)(M_DIM - 1) - 1.0f;
        float iy  = ((yl + 1.0f) * (float)M_DIM - 1.0f) * 0.5f;
        float y0f = floorf(iy);
        float wy1 = iy - y0f;
        int   r0  = (int)y0f - g0;               // in [0, 1]

        const float4* __restrict__ a = reinterpret_cast<const float4*>(sm + r0 * RSTRIDE);
        const float4* __restrict__ b = reinterpret_cast<const float4*>(sm + (r0 + 1) * RSTRIDE);
        float4* __restrict__ dst = reinterpret_cast<float4*>(sm + BL_OFF + r * RSTRIDE);

        for (int c = tid; c < VEC_PER_ROW; c += 256) {
            float4 va = a[c], vb = b[c], o;
            o.x = fmaf(wy1, vb.x - va.x, va.x);
            o.y = fmaf(wy1, vb.y - va.y, va.y);
            o.z = fmaf(wy1, vb.z - va.z, va.z);
            o.w = fmaf(wy1, vb.w - va.w, va.w);
            dst[c] = o;
        }
    }
    __syncthreads();

    // ── Gather: lr from smem (coalesced LDS.128) + 2 random scalar taps ──
    const int   xs  = tid * 4;
    const float xlb = (float)xs;
    const float RCP_SCALE = 2.0f / 1023.0f;

    #pragma unroll
    for (int r = 0; r < ROWS_PER_BLK; r++) {
        const int y = ybase + r;
        const float* __restrict__ rowb = sm + BL_OFF + r * RSTRIDE;

        float4 dv = *reinterpret_cast<const float4*>(sm + LR_OFF + r * N_DIM + xs);
        float dd[4] = {dv.x, dv.y, dv.z, dv.w};
        float res[4];

        #pragma unroll
        for (int j = 0; j < 4; j++) {
            float d  = dd[j];
            float xr = (xlb + (float)j) - d;

            float t   = fmaf(xr, RCP_SCALE, -1.0f);   // xr_normed
            float ix  = fmaf(t, 512.0f, 511.5f);      // ((t+1)*1024 - 1)*0.5
            float x0f = floorf(ix);
            float wx1 = ix - x0f;
            int   idx = (int)x0f + LPAD;   // valid lanes: in [3, 1027]; negatives only
                                           // for invalid lanes (memory-safe garbage)

            float b0 = rowb[idx];
            float b1 = rowb[idx + 1];
            float warped = fmaf(wx1, b1 - b0, b0);

            float dist = fabsf(d + warped);
            // d in [0,64) => xr = x-d <= 1023 < N always; only left OOB possible
            res[j] = (xr < 0.0f) ? INVALID_VAL : dist;
        }

        *reinterpret_cast<float4*>(out + sbase + y * N_DIM + xs) =
            make_float4(res[0], res[1], res[2], res[3]);
    }
}

extern "C" void kernel_launch(void* const* d_in, const int* in_sizes, int n_in,
                              void* d_out, int out_size)
{
    const float* lr = (const float*)d_in[0];
    const float* rl = (const float*)d_in[1];
    float* out = (float*)d_out;

    int blocks = S_DIM * (M_DIM / ROWS_PER_BLK);   // 16 * 384 = 6144
    lr_distance_kernel<<<blocks, 256>>>(lr, rl, out);
}

// round 16
// speedup vs baseline: 1.1039x; 1.0012x over previous
#include <cuda_runtime.h>
#include <cstdint>

#define S_DIM 16
#define M_DIM 768
#define N_DIM 1024
#define ROWS_PER_BLK 2
#define STAGE_ROWS 3              // exactly rows r, r+1 feed blend row r (all groups)
#define LPAD 4                    // only blend[-1] must be zero for VALID outputs
#define RPAD 4                    // only blend[1024] must be zero
#define RSTRIDE (LPAD + N_DIM + RPAD)   // 1032 floats = 4128 B (16B multiple)
#define ROW_BYTES (N_DIM * 4)     // 4096
#define RL_OFF (ROWS_PER_BLK * N_DIM)   // staged rl rows come AFTER lr rows, so
                                        // negative gather indices land in lr data
#define VEC_PER_ROW (RSTRIDE / 4)       // 258 float4 per padded row
#define INVALID_VAL 100.0f

__device__ __forceinline__ uint32_t smem_u32(const void* p) {
    return (uint32_t)__cvta_generic_to_shared(p);
}

__global__ __launch_bounds__(256) void lr_distance_kernel(
    const float* __restrict__ lr,
    const float* __restrict__ rl,
    float* __restrict__ out)
{
    // Layout: [lr row0 | lr row1 | rl row0 | rl row1 | rl row2] = 20576 B
    //   -> 8 blocks/SM (64 warps) even with driver smem reserve.
    // Blends are computed IN-PLACE: row0 <- lerp(row0,row1), row2 <- lerp(row1,row2).
    // Race-free without barriers: each column is read and written by the same thread,
    // and row1 (shared source) is never written.
    // Invalid-lane gathers (idx down to -61) read lr/staged data — memory-safe
    // garbage, always overwritten with INVALID_VAL.
    __shared__ __align__(16) float sm[RL_OFF + STAGE_ROWS * RSTRIDE];
    __shared__ __align__(8)  uint64_t mbar;

    const int tid   = threadIdx.x;
    const int bid   = blockIdx.x;
    const int s     = bid / (M_DIM / ROWS_PER_BLK);
    const int grp   = bid % (M_DIM / ROWS_PER_BLK);
    const int ybase = grp * ROWS_PER_BLK;
    // y0(y) = y-1 for y <= M/2-1, y for y >= M/2  (iy = y*M/(M-1) - 0.5)
    const int g0    = ybase - (ybase < (M_DIM / 2) ? 1 : 0);  // first staged row

    const int sbase = s * (M_DIM * N_DIM);
    const float* __restrict__ img = rl + sbase;
    const uint32_t bar = smem_u32(&mbar);

    // Thread 0: init barrier, proxy-fence, issue all bulk copies (program-ordered).
    if (tid == 0) {
        asm volatile("mbarrier.init.shared.b64 [%0], %1;" :: "r"(bar), "r"(1) : "memory");
        asm volatile("fence.proxy.async.shared::cta;" ::: "memory");
        int n_valid = 0;
        #pragma unroll
        for (int r = 0; r < STAGE_ROWS; r++) {
            int g = g0 + r;
            if (g >= 0 && g < M_DIM) n_valid++;
        }
        asm volatile("mbarrier.arrive.expect_tx.shared.b64 _, [%0], %1;"
                     :: "r"(bar), "r"((n_valid + ROWS_PER_BLK) * ROW_BYTES) : "memory");
        // lr rows (dense destinations, at the front of smem)
        #pragma unroll
        for (int r = 0; r < ROWS_PER_BLK; r++) {
            uint32_t dst = smem_u32(sm + r * N_DIM);
            const float* src = lr + sbase + (ybase + r) * N_DIM;
            asm volatile(
                "cp.async.bulk.shared::cta.global.mbarrier::complete_tx::bytes "
                "[%0], [%1], %2, [%3];"
                :: "r"(dst), "l"(src), "r"(ROW_BYTES), "r"(bar) : "memory");
        }
        // rl rows (padded destinations; LPAD*4 = 16 B keeps dst 16B aligned)
        #pragma unroll
        for (int r = 0; r < STAGE_ROWS; r++) {
            int g = g0 + r;
            if (g >= 0 && g < M_DIM) {
                uint32_t dst = smem_u32(sm + RL_OFF + r * RSTRIDE + LPAD);
                const float* src = img + g * N_DIM;
                asm volatile(
                    "cp.async.bulk.shared::cta.global.mbarrier::complete_tx::bytes "
                    "[%0], [%1], %2, [%3];"
                    :: "r"(dst), "l"(src), "r"(ROW_BYTES), "r"(bar) : "memory");
            }
        }
    }

    // Zero staged-row pads (8 floats/row: [0,4) and [1028,1032)) — 24 entries total.
    if (tid < STAGE_ROWS * (LPAD + RPAD)) {
        int r = tid / (LPAD + RPAD);
        int p = tid % (LPAD + RPAD);
        int idx = (p < LPAD) ? p : (N_DIM + p);
        sm[RL_OFF + r * RSTRIDE + idx] = 0.0f;
    }
    // Zero out-of-bounds staged rows (only first/last group of each image)
    #pragma unroll
    for (int r = 0; r < STAGE_ROWS; r++) {
        int g = g0 + r;
        if (g < 0 || g >= M_DIM) {
            for (int c = tid; c < N_DIM / 4; c += 256)
                reinterpret_cast<float4*>(sm + RL_OFF + r * RSTRIDE + LPAD)[c] =
                    make_float4(0.0f, 0.0f, 0.0f, 0.0f);
        }
    }
    __syncthreads();   // publishes pad stores + mbarrier init to all threads

    // Wait for all bulk copies (acquire orders subsequent LDS after TMA writes)
    {
        uint32_t done;
        do {
            asm volatile(
                "{\n\t.reg .pred p;\n\t"
                "mbarrier.try_wait.parity.acquire.cta.shared::cta.b64 p, [%1], %2;\n\t"
                "selp.b32 %0, 1, 0, p;\n\t}"
                : "=r"(done) : "r"(bar), "r"(0u) : "memory");
        } while (!done);
    }

    // Per-row vertical weight (blend row r reads staged rows r, r+1 — all groups)
    float wy1v[ROWS_PER_BLK];
    #pragma unroll
    for (int r = 0; r < ROWS_PER_BLK; r++) {
        const int y = ybase + r;
        float yl  = 2.0f * (float)y / (float)(M_DIM - 1) - 1.0f;
        float iy  = ((yl + 1.0f) * (float)M_DIM - 1.0f) * 0.5f;
        wy1v[r] = iy - floorf(iy);
    }

    // ── In-place vertical pre-blend, NO extra barriers ──
    //   row0[c] <- lerp(row0[c], row1[c], wy1[0])   (same-thread read->write per column)
    //   row2[c] <- lerp(row1[c], row2[c], wy1[1])
    {
        const float4* __restrict__ r0v = reinterpret_cast<const float4*>(sm + RL_OFF);
        const float4* __restrict__ r1v = reinterpret_cast<const float4*>(sm + RL_OFF + RSTRIDE);
        const float4* __restrict__ r2v = reinterpret_cast<const float4*>(sm + RL_OFF + 2 * RSTRIDE);
        float4* __restrict__ d0 = reinterpret_cast<float4*>(sm + RL_OFF);
        float4* __restrict__ d2 = reinterpret_cast<float4*>(sm + RL_OFF + 2 * RSTRIDE);

        for (int c = tid; c < VEC_PER_ROW; c += 256) {
            float4 v0 = r0v[c], v1 = r1v[c], v2 = r2v[c], o0, o2;
            float w0 = wy1v[0], w1 = wy1v[1];
            o0.x = fmaf(w0, v1.x - v0.x, v0.x);
            o0.y = fmaf(w0, v1.y - v0.y, v0.y);
            o0.z = fmaf(w0, v1.z - v0.z, v0.z);
            o0.w = fmaf(w0, v1.w - v0.w, v0.w);
            o2.x = fmaf(w1, v2.x - v1.x, v1.x);
            o2.y = fmaf(w1, v2.y - v1.y, v1.y);
            o2.z = fmaf(w1, v2.z - v1.z, v1.z);
            o2.w = fmaf(w1, v2.w - v1.w, v1.w);
            d0[c] = o0;
            d2[c] = o2;
        }
    }
    __syncthreads();   // blends visible to all threads for the gather

    // ── Gather: lr from smem (coalesced LDS.128) + 2 random scalar taps ──
    const int   xs  = tid * 4;
    const float xlb = (float)xs;
    const float RCP_SCALE = 2.0f / 1023.0f;

    #pragma unroll
    for (int r = 0; r < ROWS_PER_BLK; r++) {
        const int y = ybase + r;
        // blend0 lives in staged row0's region, blend1 in staged row2's region
        const float* __restrict__ rowb = sm + RL_OFF + (2 * r) * RSTRIDE;

        float4 dv = *reinterpret_cast<const float4*>(sm + r * N_DIM + xs);
        float dd[4] = {dv.x, dv.y, dv.z, dv.w};
        float res[4];

        #pragma unroll
        for (int j = 0; j < 4; j++) {
            float d  = dd[j];
            float xr = (xlb + (float)j) - d;

            float t   = fmaf(xr, RCP_SCALE, -1.0f);   // xr_normed
            float ix  = fmaf(t, 512.0f, 511.5f);      // ((t+1)*1024 - 1)*0.5
            float x0f = floorf(ix);
            float wx1 = ix - x0f;
            int   idx = (int)x0f + LPAD;   // valid lanes: [3, 1027]; negatives only
                                           // for invalid lanes (memory-safe garbage)

            float b0 = rowb[idx];
            float b1 = rowb[idx + 1];
            float warped = fmaf(wx1, b1 - b0, b0);

            float dist = fabsf(d + warped);
            // d in [0,64) => xr = x-d <= 1023 < N always; only left OOB possible
            res[j] = (xr < 0.0f) ? INVALID_VAL : dist;
        }

        *reinterpret_cast<float4*>(out + sbase + y * N_DIM + xs) =
            make_float4(res[0], res[1], res[2], res[3]);
    }
}

extern "C" void kernel_launch(void* const* d_in, const int* in_sizes, int n_in,
                              void* d_out, int out_size)
{
    const float* lr = (const float*)d_in[0];
    const float* rl = (const float*)d_in[1];
    float* out = (float*)d_out;

    int blocks = S_DIM * (M_DIM / ROWS_PER_BLK);   // 16 * 384 = 6144
    lr_distance_kernel<<<blocks, 256>>>(lr, rl, out);
}